// round 17
// baseline (speedup 1.0000x reference)
#include <cuda_runtime.h>
#include <cuda_bf16.h>
#include <cuda_fp16.h>
#include <math.h>

#define N_NODES 32768
#define EMB 512
#define HEADS 4
#define OUT 2048
#define NE 131072
#define NTOT (NE + N_NODES)
#define NB 32
#define HID 32

#define BM 128
#define BN 128
#define BKC 64                     // k-chunk (elems) = 128 bytes/row
#define STGH 32768                 // fp16 stage: A 16K + B 16K
#define SMEMH 67584                // >= 2*STGH (65536) AND pool staging 128*129*4+512=66560

// ---------------- scratch (static device globals) ---------------------------
__device__ __half   d_xeh[(size_t)N_NODES * EMB];        // gathered emb fp16
__device__ __half   d_xh[(size_t)N_NODES * EMB];         // x after feat linear (fp16)
__device__ __half   d_zh[(size_t)N_NODES * OUT];         // aggregated x (fp16)
__device__ __half   d_wfh[(size_t)EMB * EMB];            // W_feat^T fp16 [N][K]
__device__ __half   d_wgh[(size_t)OUT * EMB];            // W_gat^T fp16 [N][K]
__device__ float    d_wt[8 * EMB];
__device__ float    d_asrc[N_NODES * HEADS];
__device__ float    d_adst[N_NODES * HEADS];
__device__ int      d_deg[N_NODES];
__device__ int      d_off[N_NODES + 1];
__device__ int      d_pos[N_NODES];
__device__ int      d_csrc[NTOT];
__device__ float    d_calpha[(size_t)NTOT * HEADS];
__device__ int      d_bsum[32];
__device__ int      d_boff[32];
__device__ int      d_gcnt[NB];
__device__ float    d_gsum[NB * OUT];
__device__ unsigned d_gmaxE[NB * OUT];
__device__ float    d_g[NB * 2 * OUT];

__device__ __forceinline__ unsigned fenc(float f) {
    unsigned u = __float_as_uint(f);
    return (u >> 31) ? ~u : (u | 0x80000000u);
}
__device__ __forceinline__ float fdec(unsigned u) {
    u = (u >> 31) ? (u & 0x7fffffffu) : ~u;
    return __uint_as_float(u);
}
__device__ __forceinline__ void mma_f16(float* c, const unsigned* a, const unsigned* b) {
    asm volatile(
        "mma.sync.aligned.m16n8k16.row.col.f32.f16.f16.f32 "
        "{%0,%1,%2,%3}, {%4,%5,%6,%7}, {%8,%9}, {%0,%1,%2,%3};"
        : "+f"(c[0]), "+f"(c[1]), "+f"(c[2]), "+f"(c[3])
        : "r"(a[0]), "r"(a[1]), "r"(a[2]), "r"(a[3]), "r"(b[0]), "r"(b[1]));
}
__device__ __forceinline__ void ldsm_x4(unsigned* r, unsigned addr) {
    asm volatile("ldmatrix.sync.aligned.m8n8.x4.shared.b16 {%0,%1,%2,%3}, [%4];"
                 : "=r"(r[0]), "=r"(r[1]), "=r"(r[2]), "=r"(r[3]) : "r"(addr));
}
__device__ __forceinline__ void cpasync16(unsigned saddr, const void* gaddr) {
    asm volatile("cp.async.cg.shared.global [%0], [%1], 16;" :: "r"(saddr), "l"(gaddr));
}
__device__ __forceinline__ void cpcommit() { asm volatile("cp.async.commit_group;"); }
__device__ __forceinline__ void cpwaitall() { asm volatile("cp.async.wait_group 0;"); }

// ---------------- init ------------------------------------------------------
__global__ void init_kernel() {
    int i = blockIdx.x * blockDim.x + threadIdx.x;
    if (i < N_NODES) d_deg[i] = 0;
    if (i < NB * OUT) { d_gsum[i] = 0.f; d_gmaxE[i] = fenc(-INFINITY); }
    if (i < NB) d_gcnt[i] = 0;
}

// ---------------- weight prep: transpose fp32 [K][N] -> fp16 [N][K] ---------
__global__ void prepWh_kernel(const float* __restrict__ W, int K, int N,
                              __half* __restrict__ Wh) {
    __shared__ float tile[32][33];
    int kx = blockIdx.y * 32, nx = blockIdx.x * 32;
    int tx = threadIdx.x & 31, ty = threadIdx.x >> 5;
#pragma unroll
    for (int p = 0; p < 4; p++)
        tile[ty + p * 8][tx] = W[(long)(kx + ty + p * 8) * N + nx + tx];
    __syncthreads();
#pragma unroll
    for (int p = 0; p < 4; p++) {
        int nl = ty + p * 8, kl = tx;
        Wh[(long)(nx + nl) * K + kx + kl] = __float2half_rn(tile[kl][nl]);
    }
}

// ---------------- fold att vectors through W_gat ----------------------------
__global__ void prepwt_kernel(const float* __restrict__ W_gat,
                              const float* __restrict__ att_src,
                              const float* __restrict__ att_dst) {
    int k = blockIdx.x;
    int w = threadIdx.x >> 5, lane = threadIdx.x & 31;
    int hd = w & 3;
    const float* att = (w < 4) ? att_src : att_dst;
    const float* wr = W_gat + (long)k * OUT + hd * EMB;
    const float* ar = att + hd * EMB;
    float s = 0.f;
    for (int c = lane; c < EMB; c += 32) s += wr[c] * ar[c];
#pragma unroll
    for (int o = 16; o; o >>= 1) s += __shfl_down_sync(0xffffffffu, s, o);
    if (lane == 0) d_wt[w * EMB + k] = s;
}

// ---------------- gather emb rows -> fp16 -----------------------------------
__global__ void gathdec_kernel(const float* __restrict__ emb,
                               const int* __restrict__ code) {
    long i = (long)blockIdx.x * blockDim.x + threadIdx.x;
    int row = (int)(i >> 7);
    int c4 = (int)(i & 127) * 4;
    float4 v = *(const float4*)(emb + (long)code[row] * EMB + c4);
    __half2 p0 = __floats2half2_rn(v.x, v.y);
    __half2 p1 = __floats2half2_rn(v.z, v.w);
    long o = (long)row * EMB + c4;
    *(__half2*)&d_xeh[o] = p0;
    *(__half2*)&d_xeh[o + 2] = p1;
}

// ---------------- fp16 GEMM 128x128 core (2 CTA/SM) -------------------------
// POOL=false: Ch[r][c] = fp16(sum_k A*B + bias).
// POOL=true:  v = leaky_0.01(acc+bias); segment mean/max pool by batch[row].
template <bool POOL>
__global__ void __launch_bounds__(256, 2) gemm_h_kernel(
    const __half* __restrict__ Ah, int lda,
    const __half* __restrict__ Bh,
    const float* __restrict__ bias,
    __half* __restrict__ Ch, int ldc, int K,
    const int* __restrict__ batch) {
    extern __shared__ char smem[];
    unsigned sbase = (unsigned)__cvta_generic_to_shared(smem);

    int hz = blockIdx.z;
    const __half* Ap = POOL ? (Ah + hz * EMB) : Ah;
    const __half* Bp = POOL ? (Bh + (long)hz * EMB * EMB) : Bh;
    const float* bp = POOL ? (bias + hz * EMB) : bias;

    int tid = threadIdx.x, wid = tid >> 5, lane = tid & 31;
    int warp_m = wid >> 2, warp_n = wid & 3;   // 2 x 4 warps, 64x32 per warp
    int brow = blockIdx.y * BM, bcol = blockIdx.x * BN;

    const __half *agp[4], *bgp[4];
    unsigned asm_[4], bsm_[4];
#pragma unroll
    for (int p = 0; p < 4; p++) {
        int id = tid + 256 * p;
        int ar = id >> 3, ac = id & 7;
        unsigned so = ar * 128 + ((ac ^ (ar & 7)) << 4);
        agp[p] = Ap + (long)(brow + ar) * lda + ac * 8;
        asm_[p] = so;
        bgp[p] = Bp + (long)(bcol + ar) * K + ac * 8;
        bsm_[p] = 16384 + so;
    }

    float acc[4][4][4];
#pragma unroll
    for (int mi = 0; mi < 4; mi++)
#pragma unroll
        for (int ni = 0; ni < 4; ni++)
#pragma unroll
            for (int j = 0; j < 4; j++) acc[mi][ni][j] = 0.f;

    int nch = K / BKC;
    {
#pragma unroll
        for (int p = 0; p < 4; p++) {
            cpasync16(sbase + asm_[p], agp[p]);
            cpasync16(sbase + bsm_[p], bgp[p]);
        }
        cpcommit();
    }

    int a_lrow = (lane & 15), a_lchsel = (lane >> 4);
    int b_lrow = (lane & 7) + ((lane >> 4) << 3), b_lchsel = (lane >> 3) & 1;

    for (int ch = 0; ch < nch; ch++) {
        cpwaitall();
        __syncthreads();
        unsigned cur = sbase + (unsigned)(ch & 1) * STGH;
        if (ch + 1 < nch) {
            unsigned nxt = sbase + (unsigned)((ch + 1) & 1) * STGH;
            int kk = (ch + 1) * BKC;
#pragma unroll
            for (int p = 0; p < 4; p++) {
                cpasync16(nxt + asm_[p], agp[p] + kk);
                cpasync16(nxt + bsm_[p], bgp[p] + kk);
            }
            cpcommit();
        }
#pragma unroll
        for (int ks = 0; ks < 4; ks++) {
            int cb = ks << 1;
            unsigned ah[4][4];
#pragma unroll
            for (int mi = 0; mi < 4; mi++) {
                int row = warp_m * 64 + mi * 16 + a_lrow;
                int c = cb + a_lchsel;
                unsigned off = row * 128 + (((unsigned)(c ^ (row & 7))) << 4);
                ldsm_x4(ah[mi], cur + off);
            }
            unsigned bh[4][2];
#pragma unroll
            for (int p = 0; p < 2; p++) {
                int row = warp_n * 32 + p * 16 + b_lrow;
                int c = cb + b_lchsel;
                unsigned off = row * 128 + (((unsigned)(c ^ (row & 7))) << 4);
                unsigned r4[4];
                ldsm_x4(r4, cur + 16384 + off);
                bh[2 * p][0] = r4[0]; bh[2 * p][1] = r4[1];
                bh[2 * p + 1][0] = r4[2]; bh[2 * p + 1][1] = r4[3];
            }
#pragma unroll
            for (int mi = 0; mi < 4; mi++)
#pragma unroll
                for (int ni = 0; ni < 4; ni++)
                    mma_f16(acc[mi][ni], ah[mi], bh[ni]);
        }
    }
    __syncthreads();

    int g = lane >> 2, t = lane & 3;
    if (!POOL) {
#pragma unroll
        for (int mi = 0; mi < 4; mi++) {
            int r0 = brow + warp_m * 64 + mi * 16 + g;
#pragma unroll
            for (int ni = 0; ni < 4; ni++) {
                int c0 = bcol + warp_n * 32 + ni * 8 + 2 * t;
                float b0 = bp[c0], b1 = bp[c0 + 1];
                *(__half2*)&Ch[(long)r0 * ldc + c0] =
                    __floats2half2_rn(acc[mi][ni][0] + b0, acc[mi][ni][1] + b1);
                *(__half2*)&Ch[(long)(r0 + 8) * ldc + c0] =
                    __floats2half2_rn(acc[mi][ni][2] + b0, acc[mi][ni][3] + b1);
            }
        }
    } else {
        // stage leaky(acc+bias) into smem [128][129] (66560 B <= SMEMH)
        float* sp = (float*)smem;
        int* sb = (int*)(smem + 128 * 129 * 4);
#pragma unroll
        for (int mi = 0; mi < 4; mi++) {
            int rl = warp_m * 64 + mi * 16 + g;
#pragma unroll
            for (int ni = 0; ni < 4; ni++) {
                int cl = warp_n * 32 + ni * 8 + 2 * t;
                float b0 = bp[bcol + cl], b1 = bp[bcol + cl + 1];
                float v0 = acc[mi][ni][0] + b0;
                float v1 = acc[mi][ni][1] + b1;
                float v2 = acc[mi][ni][2] + b0;
                float v3 = acc[mi][ni][3] + b1;
                v0 = v0 > 0.f ? v0 : 0.01f * v0;
                v1 = v1 > 0.f ? v1 : 0.01f * v1;
                v2 = v2 > 0.f ? v2 : 0.01f * v2;
                v3 = v3 > 0.f ? v3 : 0.01f * v3;
                sp[rl * 129 + cl] = v0;
                sp[rl * 129 + cl + 1] = v1;
                sp[(rl + 8) * 129 + cl] = v2;
                sp[(rl + 8) * 129 + cl + 1] = v3;
            }
        }
        if (tid < 128) sb[tid] = batch[brow + tid];
        __syncthreads();
        {
            int grp = tid >> 7;        // 0..1 -> rows [grp*64, grp*64+64)
            int col = tid & 127;
            int r0 = grp * 64, r1 = r0 + 64;
            int gcol = hz * EMB + bcol + col;
            int curg = sb[r0];
            float s = 0.f, m = -INFINITY;
            for (int r = r0; r < r1; r++) {
                int gg = sb[r];
                if (gg != curg) {
                    atomicAdd(&d_gsum[curg * OUT + gcol], s);
                    atomicMax(&d_gmaxE[curg * OUT + gcol], fenc(m));
                    s = 0.f; m = -INFINITY; curg = gg;
                }
                float v = sp[r * 129 + col];
                s += v;
                m = fmaxf(m, v);
            }
            atomicAdd(&d_gsum[curg * OUT + gcol], s);
            atomicMax(&d_gmaxE[curg * OUT + gcol], fenc(m));
        }
    }
}

// ---------------- attention scalars from fp16 x and folded wt ---------------
__global__ void attnx_kernel() {
    __shared__ float wt[8 * EMB];
    int tid = threadIdx.x;
    for (int i = tid; i < 8 * EMB; i += 256) wt[i] = d_wt[i];
    __syncthreads();
    int w = tid >> 5, lane = tid & 31;
    int n = blockIdx.x * 8 + w;
    const __half2* xr = (const __half2*)(d_xh + (size_t)n * EMB);
    float s[8] = {0.f, 0.f, 0.f, 0.f, 0.f, 0.f, 0.f, 0.f};
#pragma unroll
    for (int i = 0; i < EMB / 64; i++) {
        int c2 = lane + 32 * i;
        float2 xv = __half22float2(xr[c2]);
#pragma unroll
        for (int q = 0; q < 8; q++) {
            s[q] += xv.x * wt[q * EMB + 2 * c2] + xv.y * wt[q * EMB + 2 * c2 + 1];
        }
    }
#pragma unroll
    for (int o = 16; o; o >>= 1)
#pragma unroll
        for (int q = 0; q < 8; q++) s[q] += __shfl_down_sync(0xffffffffu, s[q], o);
    if (lane == 0) {
        *(float4*)&d_asrc[n * 4] = make_float4(s[0], s[1], s[2], s[3]);
        *(float4*)&d_adst[n * 4] = make_float4(s[4], s[5], s[6], s[7]);
    }
}

// ---------------- count pass (edges only; side stream) ----------------------
__global__ void count_kernel(const int* __restrict__ ei) {
    int e = blockIdx.x * blockDim.x + threadIdx.x;
    if (e >= NTOT) return;
    int dst = (e < NE) ? ei[NE + e] : (e - NE);
    atomicAdd(&d_deg[dst], 1);
}

// ---------------- fast scan (3 kernels; side stream) ------------------------
__global__ void scanA_kernel() {
    int b = blockIdx.x, tid = threadIdx.x;
    int i = b * 1024 + tid;
    int v = d_deg[i];
    int lane = tid & 31, w = tid >> 5;
    int x = v;
#pragma unroll
    for (int o = 1; o < 32; o <<= 1) {
        int y = __shfl_up_sync(0xffffffffu, x, o);
        if (lane >= o) x += y;
    }
    __shared__ int ws[32];
    if (lane == 31) ws[w] = x;
    __syncthreads();
    if (w == 0) {
        int z = ws[lane];
#pragma unroll
        for (int o = 1; o < 32; o <<= 1) {
            int y = __shfl_up_sync(0xffffffffu, z, o);
            if (lane >= o) z += y;
        }
        ws[lane] = z;
    }
    __syncthreads();
    int incl = x + (w ? ws[w - 1] : 0);
    d_off[i] = incl - v;
    if (tid == 1023) d_bsum[b] = incl;
}

__global__ void scanB_kernel() {
    int lane = threadIdx.x;
    int v = d_bsum[lane];
    int x = v;
#pragma unroll
    for (int o = 1; o < 32; o <<= 1) {
        int y = __shfl_up_sync(0xffffffffu, x, o);
        if (lane >= o) x += y;
    }
    d_boff[lane] = x - v;
    if (lane == 31) d_off[N_NODES] = x;
}

__global__ void scanC_kernel(const int* __restrict__ batch) {
    int b = blockIdx.x, tid = threadIdx.x;
    int i = b * 1024 + tid;
    int o = d_off[i] + d_boff[b];
    d_off[i] = o;
    d_pos[i] = o;
    atomicAdd(&d_gcnt[batch[i]], 1);
}

// ---------------- merged: alpha compute + CSR scatter (critical path) -------
__global__ void alphascatter_kernel(const int* __restrict__ ei) {
    int e = blockIdx.x * blockDim.x + threadIdx.x;
    if (e >= NTOT) return;
    int src, dst;
    if (e < NE) { src = ei[e]; dst = ei[NE + e]; }
    else        { src = dst = e - NE; }
    float4 as = *(const float4*)&d_asrc[src * 4];
    float4 ad = *(const float4*)&d_adst[dst * 4];
    float r[4] = {as.x + ad.x, as.y + ad.y, as.z + ad.z, as.w + ad.w};
#pragma unroll
    for (int h = 0; h < 4; h++) {
        r[h] = r[h] > 0.f ? r[h] : 0.2f * r[h];
        r[h] = expf(r[h]);   // logits O(1e-2): shift-invariant softmax, no max pass
    }
    int p = atomicAdd(&d_pos[dst], 1);
    d_csrc[p] = src;
    *(float4*)&d_calpha[(size_t)p * 4] = make_float4(r[0], r[1], r[2], r[3]);
}

// ---------------- aggregation (fp16 x) -> fp16 z ----------------------------
__global__ void aggregate_kernel() {
    int dst = blockIdx.x, t = threadIdx.x;
    int c2 = t;
    float acc[4][2] = {{0.f, 0.f}, {0.f, 0.f}, {0.f, 0.f}, {0.f, 0.f}};
    float asum[4] = {0.f, 0.f, 0.f, 0.f};
    int s = d_off[dst], e = d_off[dst + 1];
    int i = s;
    for (; i + 1 < e; i += 2) {
        int src0 = d_csrc[i], src1 = d_csrc[i + 1];
        float4 al0 = *(const float4*)&d_calpha[(size_t)i * 4];
        float4 al1 = *(const float4*)&d_calpha[(size_t)(i + 1) * 4];
        __half2 h0 = *(const __half2*)(d_xh + (size_t)src0 * EMB + 2 * c2);
        __half2 h1 = *(const __half2*)(d_xh + (size_t)src1 * EMB + 2 * c2);
        float2 x0 = __half22float2(h0);
        float2 x1 = __half22float2(h1);
        acc[0][0] += al0.x * x0.x + al1.x * x1.x;
        acc[0][1] += al0.x * x0.y + al1.x * x1.y;
        acc[1][0] += al0.y * x0.x + al1.y * x1.x;
        acc[1][1] += al0.y * x0.y + al1.y * x1.y;
        acc[2][0] += al0.z * x0.x + al1.z * x1.x;
        acc[2][1] += al0.z * x0.y + al1.z * x1.y;
        acc[3][0] += al0.w * x0.x + al1.w * x1.x;
        acc[3][1] += al0.w * x0.y + al1.w * x1.y;
        asum[0] += al0.x + al1.x; asum[1] += al0.y + al1.y;
        asum[2] += al0.z + al1.z; asum[3] += al0.w + al1.w;
    }
    if (i < e) {
        int src0 = d_csrc[i];
        float4 al0 = *(const float4*)&d_calpha[(size_t)i * 4];
        float2 x0 = __half22float2(*(const __half2*)(d_xh + (size_t)src0 * EMB + 2 * c2));
        acc[0][0] += al0.x * x0.x; acc[0][1] += al0.x * x0.y;
        acc[1][0] += al0.y * x0.x; acc[1][1] += al0.y * x0.y;
        acc[2][0] += al0.z * x0.x; acc[2][1] += al0.z * x0.y;
        acc[3][0] += al0.w * x0.x; acc[3][1] += al0.w * x0.y;
        asum[0] += al0.x; asum[1] += al0.y; asum[2] += al0.z; asum[3] += al0.w;
    }
#pragma unroll
    for (int hd = 0; hd < 4; hd++) {
        float inv = 1.f / (asum[hd] + 1e-16f);
        __half2 hp = __floats2half2_rn(acc[hd][0] * inv, acc[hd][1] * inv);
        *(__half2*)&d_zh[((size_t)dst * 4 + hd) * EMB + 2 * c2] = hp;
    }
}

// ---------------- finalize pooled features ----------------------------------
__global__ void gfinal_kernel() {
    int i = blockIdx.x * blockDim.x + threadIdx.x;
    int b = i >> 11, c = i & (OUT - 1);
    float cnt = (float)d_gcnt[b];
    d_g[b * 2 * OUT + c] = d_gsum[i] / fmaxf(cnt, 1.f);
    d_g[b * 2 * OUT + OUT + c] = fdec(d_gmaxE[i]);
}

// ---------------- head MLPs -------------------------------------------------
__global__ void mlp_kernel(const float* __restrict__ W1r, const float* __restrict__ b1r,
                           const float* __restrict__ W2r, const float* __restrict__ b2r,
                           const float* __restrict__ W1m, const float* __restrict__ b1m,
                           const float* __restrict__ W2m, const float* __restrict__ b2m,
                           float* __restrict__ out) {
    int b = blockIdx.x, task = blockIdx.y;
    const float* W1 = task ? W1m : W1r;
    const float* b1 = task ? b1m : b1r;
    const float* W2 = task ? W2m : W2r;
    const float* b2 = task ? b2m : b2r;
    __shared__ float gs[2 * OUT];
    __shared__ float part[128];
    int t = threadIdx.x;
    for (int k = t; k < 2 * OUT; k += 128) gs[k] = d_g[b * 2 * OUT + k];
    __syncthreads();
    int j = t & 31, seg = t >> 5;
    float s = 0.f;
    for (int k = seg; k < 2 * OUT; k += 4) s += gs[k] * W1[k * HID + j];
    part[t] = s;
    __syncthreads();
    if (t < 32) {
        float hj = part[t] + part[t + 32] + part[t + 64] + part[t + 96] + b1[t];
        hj = fmaxf(hj, 0.f);
        float p = hj * W2[t];
#pragma unroll
        for (int o = 16; o; o >>= 1) p += __shfl_down_sync(0xffffffffu, p, o);
        if (t == 0) out[task * NB + b] = p + b2[0];
    }
}

// ---------------- launch ----------------------------------------------------
extern "C" void kernel_launch(void* const* d_in, const int* in_sizes, int n_in,
                              void* d_out, int out_size) {
    const int*   code     = (const int*)d_in[0];
    const int*   ei       = (const int*)d_in[1];
    const int*   batch    = (const int*)d_in[2];
    const float* emb      = (const float*)d_in[3];
    const float* W_feat   = (const float*)d_in[4];
    const float* b_feat   = (const float*)d_in[5];
    const float* W_gat    = (const float*)d_in[6];
    const float* att_src  = (const float*)d_in[7];
    const float* att_dst  = (const float*)d_in[8];
    const float* bias_gat = (const float*)d_in[9];
    const float* W1r = (const float*)d_in[10];
    const float* b1r = (const float*)d_in[11];
    const float* W2r = (const float*)d_in[12];
    const float* b2r = (const float*)d_in[13];
    const float* W1m = (const float*)d_in[14];
    const float* b1m = (const float*)d_in[15];
    const float* W2m = (const float*)d_in[16];
    const float* b2m = (const float*)d_in[17];
    float* out = (float*)d_out;

    static cudaStream_t s2 = nullptr;
    static cudaEvent_t evFork = nullptr, evWt = nullptr, evScan = nullptr;
    static int attr_done = 0;
    if (!attr_done) {
        cudaFuncSetAttribute(gemm_h_kernel<false>,
                             cudaFuncAttributeMaxDynamicSharedMemorySize, SMEMH);
        cudaFuncSetAttribute(gemm_h_kernel<true>,
                             cudaFuncAttributeMaxDynamicSharedMemorySize, SMEMH);
        cudaStreamCreateWithFlags(&s2, cudaStreamNonBlocking);
        cudaEventCreateWithFlags(&evFork, cudaEventDisableTiming);
        cudaEventCreateWithFlags(&evWt, cudaEventDisableTiming);
        cudaEventCreateWithFlags(&evScan, cudaEventDisableTiming);
        attr_done = 1;
    }

    void *p0, *p2, *p3, *p7, *p8;
    cudaGetSymbolAddress(&p0, d_xeh);
    cudaGetSymbolAddress(&p2, d_xh);
    cudaGetSymbolAddress(&p3, d_zh);
    cudaGetSymbolAddress(&p7, d_wfh);
    cudaGetSymbolAddress(&p8, d_wgh);
    __half* xeh = (__half*)p0;
    __half* xh  = (__half*)p2;
    __half* zh  = (__half*)p3;
    __half* wfh = (__half*)p7;
    __half* wgh = (__half*)p8;

    // ---- fork side stream ----
    cudaEventRecord(evFork, 0);
    cudaStreamWaitEvent(s2, evFork, 0);

    // side stream: GAT weight prep + CSR build (independent of x)
    prepwt_kernel<<<EMB, 256, 0, s2>>>(W_gat, att_src, att_dst);
    prepWh_kernel<<<dim3(OUT / 32, EMB / 32), 256, 0, s2>>>(W_gat, EMB, OUT, wgh);
    cudaEventRecord(evWt, s2);
    init_kernel<<<(N_NODES * HEADS + 255) / 256, 256, 0, s2>>>();
    count_kernel<<<(NTOT + 255) / 256, 256, 0, s2>>>(ei);
    scanA_kernel<<<32, 1024, 0, s2>>>();
    scanB_kernel<<<1, 32, 0, s2>>>();
    scanC_kernel<<<32, 1024, 0, s2>>>(batch);
    cudaEventRecord(evScan, s2);

    // main stream: x pipeline
    prepWh_kernel<<<dim3(EMB / 32, EMB / 32), 256>>>(W_feat, EMB, EMB, wfh);
    gathdec_kernel<<<(N_NODES * EMB / 4) / 256, 256>>>(emb, code);
    gemm_h_kernel<false><<<dim3(EMB / BN, N_NODES / BM, 1), 256, SMEMH>>>(
        xeh, EMB, wfh, b_feat, xh, EMB, EMB, nullptr);

    cudaStreamWaitEvent(0, evWt, 0);
    attnx_kernel<<<N_NODES / 8, 256>>>();

    cudaStreamWaitEvent(0, evScan, 0);
    alphascatter_kernel<<<(NTOT + 255) / 256, 256>>>(ei);

    aggregate_kernel<<<N_NODES, 256>>>();

    gemm_h_kernel<true><<<dim3(EMB / BN, N_NODES / BM, HEADS), 256, SMEMH>>>(
        zh, OUT, wgh, bias_gat, nullptr, 0, EMB, batch);

    gfinal_kernel<<<(NB * OUT) / 256, 256>>>();

    mlp_kernel<<<dim3(NB, 2), 128>>>(W1r, b1r, W2r, b2r, W1m, b1m, W2m, b2m, out);
}